// round 1
// baseline (speedup 1.0000x reference)
#include <cuda_runtime.h>
#include <math.h>

#define NN 100000
#define DD 64
#define EE 1600000
#define ETOT (EE + NN)

// ---- scratch (device globals; no allocation allowed) ----
__device__ float g_h[NN * DD];     // transformed features per layer
__device__ float g_x1[NN * DD];    // layer-1 output
__device__ float g_x2[NN * DD];    // layer-2 output
__device__ float g_es[NN];         // per-node src attention score
__device__ float g_ed[NN];         // per-node dst attention score
__device__ int   g_counts[NN];
__device__ int   g_rowptr[NN + 1];
__device__ int   g_cursor[NN];
__device__ int   g_csr[ETOT];      // src node ids grouped by dst

// ---- init: d_out = emb (mean accumulator), counts = 1 (self loop) ----
__global__ void k_init(const float* __restrict__ emb, float* __restrict__ out) {
    int i = blockIdx.x * blockDim.x + threadIdx.x;
    if (i < NN * DD) out[i] = emb[i];
    if (i < NN) g_counts[i] = 1;
}

// ---- CSR: count in-degree ----
__global__ void k_count(const int* __restrict__ dsts) {
    int i = blockIdx.x * blockDim.x + threadIdx.x;
    if (i < EE) atomicAdd(&g_counts[dsts[i]], 1);
}

// ---- CSR: exclusive scan (single block, 3 phases) ----
__global__ void __launch_bounds__(1024) k_scan() {
    __shared__ int sh[1024];
    int t = threadIdx.x;
    const int CH = (NN + 1023) / 1024;
    int beg = t * CH;
    int end = beg + CH; if (end > NN) end = NN;
    int s = 0;
    for (int i = beg; i < end; i++) s += g_counts[i];
    sh[t] = s;
    __syncthreads();
    for (int off = 1; off < 1024; off <<= 1) {
        int v = (t >= off) ? sh[t - off] : 0;
        __syncthreads();
        sh[t] += v;
        __syncthreads();
    }
    int run = (t == 0) ? 0 : sh[t - 1];
    for (int i = beg; i < end; i++) {
        g_rowptr[i] = run;
        g_cursor[i] = run;
        run += g_counts[i];
    }
    if (t == 1023) g_rowptr[NN] = sh[1023];
}

// ---- CSR: scatter src ids into dst-grouped buckets (+ self loops) ----
__global__ void k_fill(const int* __restrict__ srcs, const int* __restrict__ dsts) {
    int i = blockIdx.x * blockDim.x + threadIdx.x;
    if (i >= ETOT) return;
    int s, d;
    if (i < EE) { s = srcs[i]; d = dsts[i]; }
    else        { s = d = i - EE; }
    int pos = atomicAdd(&g_cursor[d], 1);
    g_csr[pos] = s;
}

// ---- per-layer transform: h = x @ W ; es = h.a_s ; ed = h.a_d ----
// warp per row; W + attention vectors staged in shared memory
__global__ void __launch_bounds__(256) k_transform(
    int layer, const float* __restrict__ emb,
    const float* __restrict__ W,
    const float* __restrict__ a_s, const float* __restrict__ a_d)
{
    __shared__ float Wsh[DD * DD];
    __shared__ float ash[DD];
    __shared__ float adh[DD];
    int tid = threadIdx.x;
    for (int i = tid; i < DD * DD; i += 256) Wsh[i] = W[i];
    if (tid < DD) { ash[tid] = a_s[tid]; adh[tid] = a_d[tid]; }
    __syncthreads();

    const float* x = (layer == 0) ? emb : (layer == 1 ? g_x1 : g_x2);

    int lane = tid & 31;
    int row = blockIdx.x * 8 + (tid >> 5);
    if (row >= NN) return;

    const float* xr = x + row * DD;
    float x0 = xr[lane];
    float x1 = xr[lane + 32];
    float acc0 = 0.f, acc1 = 0.f;
#pragma unroll
    for (int k = 0; k < 32; k++) {
        float xv = __shfl_sync(0xffffffffu, x0, k);
        acc0 = fmaf(xv, Wsh[k * DD + lane], acc0);
        acc1 = fmaf(xv, Wsh[k * DD + lane + 32], acc1);
    }
#pragma unroll
    for (int k = 0; k < 32; k++) {
        float xv = __shfl_sync(0xffffffffu, x1, k);
        acc0 = fmaf(xv, Wsh[(k + 32) * DD + lane], acc0);
        acc1 = fmaf(xv, Wsh[(k + 32) * DD + lane + 32], acc1);
    }
    g_h[row * DD + lane] = acc0;
    g_h[row * DD + lane + 32] = acc1;

    float ps = acc0 * ash[lane] + acc1 * ash[lane + 32];
    float pd = acc0 * adh[lane] + acc1 * adh[lane + 32];
#pragma unroll
    for (int o = 16; o > 0; o >>= 1) {
        ps += __shfl_xor_sync(0xffffffffu, ps, o);
        pd += __shfl_xor_sync(0xffffffffu, pd, o);
    }
    if (lane == 0) { g_es[row] = ps; g_ed[row] = pd; }
}

// ---- per-layer aggregate: warp per destination node ----
// softmax-weighted sum of h[src] without atomics; writes next x and mean acc
__global__ void __launch_bounds__(256) k_agg(
    int layer, const float* __restrict__ bias, float* __restrict__ mean_out)
{
    int tid = threadIdx.x;
    int lane = tid & 31;
    int n = blockIdx.x * 8 + (tid >> 5);
    if (n >= NN) return;

    int beg = g_rowptr[n];
    int end = g_rowptr[n + 1];
    float edn = g_ed[n];

    // pass 1: segment max (lanes parallel over edges)
    float m = -3.4e38f;
    for (int k = beg + lane; k < end; k += 32) {
        int s = g_csr[k];
        float e = g_es[s] + edn;
        e = (e > 0.f) ? e : 0.2f * e;
        m = fmaxf(m, e);
    }
#pragma unroll
    for (int o = 16; o > 0; o >>= 1) m = fmaxf(m, __shfl_xor_sync(0xffffffffu, m, o));

    // pass 2: edges sequential, lanes parallel over D (float2 per lane)
    float denom = 0.f;
    float ax = 0.f, ay = 0.f;
    const float2* h2 = (const float2*)g_h;
    for (int k = beg; k < end; k++) {
        int s = g_csr[k];                 // broadcast load
        float e = g_es[s] + edn;
        e = (e > 0.f) ? e : 0.2f * e;
        float w = __expf(e - m);
        denom += w;
        float2 hv = h2[s * 32 + lane];    // coalesced 256B/warp gather
        ax = fmaf(w, hv.x, ax);
        ay = fmaf(w, hv.y, ay);
    }
    float inv = 1.f / (denom + 1e-16f);
    float vx = ax * inv + bias[2 * lane];
    float vy = ay * inv + bias[2 * lane + 1];
    // ELU
    vx = (vx > 0.f) ? vx : expm1f(vx);
    vy = (vy > 0.f) ? vy : expm1f(vy);

    float2* m2 = (float2*)mean_out;
    float2 mo = m2[n * 32 + lane];
    mo.x += vx; mo.y += vy;
    if (layer == 2) {
        mo.x *= 0.25f; mo.y *= 0.25f;     // mean over {emb, x1, x2, x3}
    } else {
        float2* xo = (float2*)((layer == 0) ? g_x1 : g_x2);
        xo[n * 32 + lane] = make_float2(vx, vy);
    }
    m2[n * 32 + lane] = mo;
}

extern "C" void kernel_launch(void* const* d_in, const int* in_sizes, int n_in,
                              void* d_out, int out_size) {
    const int*   ei   = (const int*)d_in[0];    // [2, E]
    const float* emb  = (const float*)d_in[1];  // [N, D]
    const float* W    = (const float*)d_in[2];  // [L, D, D]
    const float* a_s  = (const float*)d_in[3];  // [L, D]
    const float* a_d  = (const float*)d_in[4];  // [L, D]
    const float* bias = (const float*)d_in[5];  // [L, D]
    float* out = (float*)d_out;

    const int* srcs = ei;
    const int* dsts = ei + EE;

    k_init<<<(NN * DD + 255) / 256, 256>>>(emb, out);
    k_count<<<(EE + 255) / 256, 256>>>(dsts);
    k_scan<<<1, 1024>>>();
    k_fill<<<(ETOT + 255) / 256, 256>>>(srcs, dsts);

    for (int l = 0; l < 3; l++) {
        k_transform<<<(NN + 7) / 8, 256>>>(l, emb, W + l * DD * DD,
                                           a_s + l * DD, a_d + l * DD);
        k_agg<<<(NN + 7) / 8, 256>>>(l, bias + l * DD, out);
    }
}

// round 3
// speedup vs baseline: 2.2367x; 2.2367x over previous
#include <cuda_runtime.h>
#include <math.h>

#define NN 100000
#define DD 64
#define EE 1600000
#define ETOT (EE + NN)
#define NB_SCAN 391   // ceil(NN/256)

// ---- scratch ----
__device__ float g_h[NN * DD];
__device__ float g_x1[NN * DD];
__device__ float g_x2[NN * DD];
__device__ float g_es[NN];
__device__ float g_ed[NN];
__device__ int   g_counts[NN];
__device__ int   g_rowptr[NN + 1];
__device__ int   g_cursor[NN];
__device__ int   g_csr[ETOT];
__device__ int   g_bsum[NB_SCAN];
__device__ float g_pmax[128];

// ---- init: out = emb (mean accumulator); counts = 1 (self loop) ----
__global__ void k_init(const float* __restrict__ emb, float* __restrict__ out) {
    int i = blockIdx.x * blockDim.x + threadIdx.x;
    if (i < NN * DD) out[i] = emb[i];
    if (i < NN) g_counts[i] = 1;
}

// ---- in-degree count (int4 loads) ----
__global__ void k_count(const int* __restrict__ dsts) {
    int i = blockIdx.x * blockDim.x + threadIdx.x;
    if (i >= EE / 4) return;
    int4 d = ((const int4*)dsts)[i];
    atomicAdd(&g_counts[d.x], 1);
    atomicAdd(&g_counts[d.y], 1);
    atomicAdd(&g_counts[d.z], 1);
    atomicAdd(&g_counts[d.w], 1);
}

// ---- block sums of counts (coalesced) ----
__global__ void __launch_bounds__(256) k_bsum() {
    __shared__ int sh[256];
    int t = threadIdx.x;
    int i = blockIdx.x * 256 + t;
    sh[t] = (i < NN) ? g_counts[i] : 0;
    __syncthreads();
    for (int o = 128; o > 0; o >>= 1) {
        if (t < o) sh[t] += sh[t + o];
        __syncthreads();
    }
    if (t == 0) g_bsum[blockIdx.x] = sh[0];
}

// ---- rowptr: per-block offset from bsums + local scan ----
__global__ void __launch_bounds__(256) k_fillptr() {
    __shared__ int sh[256];
    __shared__ int wsum[8];
    __shared__ int s_off;
    int t = threadIdx.x, b = blockIdx.x;
    int part = 0;
    for (int j = t; j < b; j += 256) part += g_bsum[j];
    sh[t] = part;
    __syncthreads();
    for (int o = 128; o > 0; o >>= 1) {
        if (t < o) sh[t] += sh[t + o];
        __syncthreads();
    }
    if (t == 0) s_off = sh[0];
    __syncthreads();

    int i = b * 256 + t;
    int c = (i < NN) ? g_counts[i] : 0;
    int lane = t & 31, w = t >> 5;
    int v = c;
#pragma unroll
    for (int o = 1; o < 32; o <<= 1) {
        int u = __shfl_up_sync(0xffffffffu, v, o);
        if (lane >= o) v += u;
    }
    if (lane == 31) wsum[w] = v;
    __syncthreads();
    if (t == 0) {
        int run = 0;
#pragma unroll
        for (int j = 0; j < 8; j++) { int tmp = wsum[j]; wsum[j] = run; run += tmp; }
    }
    __syncthreads();
    int excl = s_off + wsum[w] + v - c;
    if (i < NN) {
        g_rowptr[i] = excl;
        g_cursor[i] = excl;
        if (i == NN - 1) g_rowptr[NN] = excl + c;
    }
}

// ---- scatter src ids into dst buckets (+ self loops) ----
__global__ void k_fill(const int* __restrict__ srcs, const int* __restrict__ dsts) {
    int i = blockIdx.x * blockDim.x + threadIdx.x;
    if (i >= ETOT) return;
    int s, d;
    if (i < EE) { s = srcs[i]; d = dsts[i]; }
    else        { s = d = i - EE; }
    int pos = atomicAdd(&g_cursor[d], 1);
    g_csr[pos] = s;
}

// ---- transform: h = x@W ; es = h.a_s ; ed = h.a_d  (64x64 tile GEMM) ----
__global__ void __launch_bounds__(256) k_transform(
    int layer, const float* __restrict__ emb,
    const float* __restrict__ W,
    const float* __restrict__ a_s, const float* __restrict__ a_d)
{
    __shared__ float Xs[64 * 64];
    __shared__ float Ws[64 * 64];
    __shared__ float ash[64];
    __shared__ float adh[64];
    const float* x = (layer == 0) ? emb : (layer == 1 ? g_x1 : g_x2);
    int tid = threadIdx.x;
    int rb = blockIdx.x * 64;

    float4* Ws4 = (float4*)Ws;
    const float4* Wg4 = (const float4*)W;
#pragma unroll
    for (int j = tid; j < 1024; j += 256) Ws4[j] = Wg4[j];
    if (tid < 64) { ash[tid] = a_s[tid]; adh[tid] = a_d[tid]; }

    float4* Xs4 = (float4*)Xs;
    const float4* Xg4 = (const float4*)x;
    int nrows = NN - rb; if (nrows > 64) nrows = 64;
#pragma unroll
    for (int j = tid; j < 1024; j += 256) {
        int r = j >> 4;
        Xs4[j] = (r < nrows) ? Xg4[rb * 16 + j] : make_float4(0.f, 0.f, 0.f, 0.f);
    }
    __syncthreads();

    int tx = tid & 15, ty = tid >> 4;   // tx: 4-col group, ty: 4-row group
    float4 acc[4];
#pragma unroll
    for (int i = 0; i < 4; i++) acc[i] = make_float4(0.f, 0.f, 0.f, 0.f);

#pragma unroll
    for (int k4 = 0; k4 < 16; k4++) {
        float4 wv0 = Ws4[(4 * k4 + 0) * 16 + tx];
        float4 wv1 = Ws4[(4 * k4 + 1) * 16 + tx];
        float4 wv2 = Ws4[(4 * k4 + 2) * 16 + tx];
        float4 wv3 = Ws4[(4 * k4 + 3) * 16 + tx];
#pragma unroll
        for (int i = 0; i < 4; i++) {
            float4 xv = Xs4[(ty * 4 + i) * 16 + k4];
            acc[i].x = fmaf(xv.x, wv0.x, acc[i].x);
            acc[i].y = fmaf(xv.x, wv0.y, acc[i].y);
            acc[i].z = fmaf(xv.x, wv0.z, acc[i].z);
            acc[i].w = fmaf(xv.x, wv0.w, acc[i].w);
            acc[i].x = fmaf(xv.y, wv1.x, acc[i].x);
            acc[i].y = fmaf(xv.y, wv1.y, acc[i].y);
            acc[i].z = fmaf(xv.y, wv1.z, acc[i].z);
            acc[i].w = fmaf(xv.y, wv1.w, acc[i].w);
            acc[i].x = fmaf(xv.z, wv2.x, acc[i].x);
            acc[i].y = fmaf(xv.z, wv2.y, acc[i].y);
            acc[i].z = fmaf(xv.z, wv2.z, acc[i].z);
            acc[i].w = fmaf(xv.z, wv2.w, acc[i].w);
            acc[i].x = fmaf(xv.w, wv3.x, acc[i].x);
            acc[i].y = fmaf(xv.w, wv3.y, acc[i].y);
            acc[i].z = fmaf(xv.w, wv3.z, acc[i].z);
            acc[i].w = fmaf(xv.w, wv3.w, acc[i].w);
        }
    }

    // store h (coalesced float4)
    float4* Hg4 = (float4*)g_h;
#pragma unroll
    for (int i = 0; i < 4; i++) {
        int r = ty * 4 + i;
        if (r < nrows) Hg4[(rb + r) * 16 + tx] = acc[i];
    }

    // es/ed: partial dot over this thread's 4 cols, reduce over 16 tx lanes
    float4 as4 = ((const float4*)ash)[tx];
    float4 ad4 = ((const float4*)adh)[tx];
#pragma unroll
    for (int i = 0; i < 4; i++) {
        float ps = acc[i].x * as4.x + acc[i].y * as4.y + acc[i].z * as4.z + acc[i].w * as4.w;
        float pd = acc[i].x * ad4.x + acc[i].y * ad4.y + acc[i].z * ad4.z + acc[i].w * ad4.w;
#pragma unroll
        for (int o = 8; o > 0; o >>= 1) {
            ps += __shfl_xor_sync(0xffffffffu, ps, o);
            pd += __shfl_xor_sync(0xffffffffu, pd, o);
        }
        int r = ty * 4 + i;
        if (tx == 0 && r < nrows) { g_es[rb + r] = ps; g_ed[rb + r] = pd; }
    }
}

// ---- per-layer partial max of es (128 blocks) ----
__global__ void __launch_bounds__(256) k_gmax() {
    __shared__ float sh[256];
    int t = threadIdx.x;
    float m = -3.4e38f;
    for (int i = blockIdx.x * 256 + t; i < NN; i += 128 * 256) m = fmaxf(m, g_es[i]);
    sh[t] = m;
    __syncthreads();
    for (int o = 128; o > 0; o >>= 1) {
        if (t < o) sh[t] = fmaxf(sh[t], sh[t + o]);
        __syncthreads();
    }
    if (t == 0) g_pmax[blockIdx.x] = sh[0];
}

// ---- aggregate: warp per node, 2 half-warps = 2 edges/iter, no max pass ----
__global__ void __launch_bounds__(256) k_agg(
    int layer, const float* __restrict__ bias, float* __restrict__ mean_out)
{
    __shared__ float smax[128];
    __shared__ float sbias[64];
    __shared__ float s_gmax;
    int tid = threadIdx.x;
    if (tid < 128) smax[tid] = g_pmax[tid];
    if (tid < 64) sbias[tid] = bias[tid];
    __syncthreads();
    if (tid < 32) {
        float m = fmaxf(fmaxf(smax[tid], smax[tid + 32]),
                        fmaxf(smax[tid + 64], smax[tid + 96]));
#pragma unroll
        for (int o = 16; o > 0; o >>= 1) m = fmaxf(m, __shfl_xor_sync(0xffffffffu, m, o));
        if (tid == 0) s_gmax = m;
    }
    __syncthreads();

    int lane = tid & 31;
    int n = blockIdx.x * 8 + (tid >> 5);
    if (n >= NN) return;

    int beg = g_rowptr[n];
    int end = g_rowptr[n + 1];
    float edn = g_ed[n];
    float gm = s_gmax + edn;
    float m = (gm > 0.f) ? gm : 0.2f * gm;   // lrelu monotone => >= segment max

    int half = lane >> 4, hl = lane & 15;
    float denom = 0.f;
    float4 acc = make_float4(0.f, 0.f, 0.f, 0.f);
    const float4* h4 = (const float4*)g_h;

#pragma unroll 2
    for (int k = beg + half; k < end; k += 2) {
        int s = __ldg(&g_csr[k]);
        float e = __ldg(&g_es[s]) + edn;
        e = (e > 0.f) ? e : 0.2f * e;
        float w = __expf(e - m);
        denom += w;
        float4 hv = h4[s * 16 + hl];
        acc.x = fmaf(w, hv.x, acc.x);
        acc.y = fmaf(w, hv.y, acc.y);
        acc.z = fmaf(w, hv.z, acc.z);
        acc.w = fmaf(w, hv.w, acc.w);
    }
    denom += __shfl_xor_sync(0xffffffffu, denom, 16);
    acc.x += __shfl_xor_sync(0xffffffffu, acc.x, 16);
    acc.y += __shfl_xor_sync(0xffffffffu, acc.y, 16);
    acc.z += __shfl_xor_sync(0xffffffffu, acc.z, 16);
    acc.w += __shfl_xor_sync(0xffffffffu, acc.w, 16);

    if (half == 0) {
        float inv = 1.f / (denom + 1e-16f);
        float4 b4 = ((const float4*)sbias)[hl];
        float4 v;
        v.x = acc.x * inv + b4.x;
        v.y = acc.y * inv + b4.y;
        v.z = acc.z * inv + b4.z;
        v.w = acc.w * inv + b4.w;
        v.x = (v.x > 0.f) ? v.x : expm1f(v.x);
        v.y = (v.y > 0.f) ? v.y : expm1f(v.y);
        v.z = (v.z > 0.f) ? v.z : expm1f(v.z);
        v.w = (v.w > 0.f) ? v.w : expm1f(v.w);

        float4* m4 = (float4*)mean_out;
        float4 mo = m4[n * 16 + hl];
        mo.x += v.x; mo.y += v.y; mo.z += v.z; mo.w += v.w;
        if (layer == 2) {
            mo.x *= 0.25f; mo.y *= 0.25f; mo.z *= 0.25f; mo.w *= 0.25f;
        } else {
            float4* xo = (float4*)((layer == 0) ? g_x1 : g_x2);
            xo[n * 16 + hl] = v;
        }
        m4[n * 16 + hl] = mo;
    }
}

extern "C" void kernel_launch(void* const* d_in, const int* in_sizes, int n_in,
                              void* d_out, int out_size) {
    const int*   ei   = (const int*)d_in[0];
    const float* emb  = (const float*)d_in[1];
    const float* W    = (const float*)d_in[2];
    const float* a_s  = (const float*)d_in[3];
    const float* a_d  = (const float*)d_in[4];
    const float* bias = (const float*)d_in[5];
    float* out = (float*)d_out;

    const int* srcs = ei;
    const int* dsts = ei + EE;

    k_init<<<(NN * DD + 255) / 256, 256>>>(emb, out);
    k_count<<<(EE / 4 + 255) / 256, 256>>>(dsts);
    k_bsum<<<NB_SCAN, 256>>>();
    k_fillptr<<<NB_SCAN, 256>>>();
    k_fill<<<(ETOT + 255) / 256, 256>>>(srcs, dsts);

    for (int l = 0; l < 3; l++) {
        k_transform<<<(NN + 63) / 64, 256>>>(l, emb, W + l * DD * DD,
                                             a_s + l * DD, a_d + l * DD);
        k_gmax<<<128, 256>>>();
        k_agg<<<(NN + 7) / 8, 256>>>(l, bias + l * DD, out);
    }
}

// round 4
// speedup vs baseline: 2.3592x; 1.0548x over previous
#include <cuda_runtime.h>
#include <cuda_fp16.h>
#include <math.h>

#define NN 100000
#define DD 64
#define EE 1600000
#define ETOT (EE + NN)
#define NB_SCAN 391   // ceil(NN/256)

// ---- scratch ----
__device__ __half g_h16[NN * DD];   // transformed features (payload, fp16)
__device__ float  g_x1[NN * DD];
__device__ float  g_x2[NN * DD];
__device__ float  g_es[NN];
__device__ float  g_ed[NN];
__device__ int    g_counts[NN];
__device__ int    g_rowptr[NN + 1];
__device__ int    g_cursor[NN];
__device__ int    g_csr[ETOT];
__device__ int    g_bsum[NB_SCAN];
__device__ unsigned g_gmaxu[3];     // encoded per-layer global max of es

// monotone float <-> orderable uint
__device__ __forceinline__ unsigned fenc(float f) {
    unsigned b = __float_as_uint(f);
    return (b & 0x80000000u) ? ~b : (b | 0x80000000u);
}
__device__ __forceinline__ float fdec(unsigned e) {
    return __uint_as_float((e & 0x80000000u) ? (e ^ 0x80000000u) : ~e);
}

// ---- init: out = emb (float4), counts = 1, reset gmax ----
__global__ void k_init(const float4* __restrict__ emb4, float4* __restrict__ out4) {
    int i = blockIdx.x * blockDim.x + threadIdx.x;
    if (i < NN * DD / 4) out4[i] = emb4[i];
    if (i < NN) g_counts[i] = 1;
    if (i < 3) g_gmaxu[i] = 0u;
}

// ---- in-degree count (int4 loads) ----
__global__ void k_count(const int* __restrict__ dsts) {
    int i = blockIdx.x * blockDim.x + threadIdx.x;
    if (i >= EE / 4) return;
    int4 d = ((const int4*)dsts)[i];
    atomicAdd(&g_counts[d.x], 1);
    atomicAdd(&g_counts[d.y], 1);
    atomicAdd(&g_counts[d.z], 1);
    atomicAdd(&g_counts[d.w], 1);
}

// ---- block sums of counts ----
__global__ void __launch_bounds__(256) k_bsum() {
    __shared__ int sh[256];
    int t = threadIdx.x;
    int i = blockIdx.x * 256 + t;
    sh[t] = (i < NN) ? g_counts[i] : 0;
    __syncthreads();
    for (int o = 128; o > 0; o >>= 1) {
        if (t < o) sh[t] += sh[t + o];
        __syncthreads();
    }
    if (t == 0) g_bsum[blockIdx.x] = sh[0];
}

// ---- rowptr: per-block offset + local scan ----
__global__ void __launch_bounds__(256) k_fillptr() {
    __shared__ int sh[256];
    __shared__ int wsum[8];
    __shared__ int s_off;
    int t = threadIdx.x, b = blockIdx.x;
    int part = 0;
    for (int j = t; j < b; j += 256) part += g_bsum[j];
    sh[t] = part;
    __syncthreads();
    for (int o = 128; o > 0; o >>= 1) {
        if (t < o) sh[t] += sh[t + o];
        __syncthreads();
    }
    if (t == 0) s_off = sh[0];
    __syncthreads();

    int i = b * 256 + t;
    int c = (i < NN) ? g_counts[i] : 0;
    int lane = t & 31, w = t >> 5;
    int v = c;
#pragma unroll
    for (int o = 1; o < 32; o <<= 1) {
        int u = __shfl_up_sync(0xffffffffu, v, o);
        if (lane >= o) v += u;
    }
    if (lane == 31) wsum[w] = v;
    __syncthreads();
    if (t == 0) {
        int run = 0;
#pragma unroll
        for (int j = 0; j < 8; j++) { int tmp = wsum[j]; wsum[j] = run; run += tmp; }
    }
    __syncthreads();
    int excl = s_off + wsum[w] + v - c;
    if (i < NN) {
        g_rowptr[i] = excl;
        g_cursor[i] = excl;
        if (i == NN - 1) g_rowptr[NN] = excl + c;
    }
}

// ---- scatter src ids into dst buckets (+ self loops) ----
__global__ void k_fill(const int* __restrict__ srcs, const int* __restrict__ dsts) {
    int i = blockIdx.x * blockDim.x + threadIdx.x;
    if (i >= ETOT) return;
    int s, d;
    if (i < EE) { s = srcs[i]; d = dsts[i]; }
    else        { s = d = i - EE; }
    int pos = atomicAdd(&g_cursor[d], 1);
    g_csr[pos] = s;
}

// ---- transform: h = x@W (fp16 store); es/ed; fused block-max of es ----
__global__ void __launch_bounds__(256) k_transform(
    int layer, const float* __restrict__ emb,
    const float* __restrict__ W,
    const float* __restrict__ a_s, const float* __restrict__ a_d)
{
    __shared__ float Xs[64 * 64];
    __shared__ float Ws[64 * 64];
    __shared__ float ash[64];
    __shared__ float adh[64];
    __shared__ float smax[8];
    const float* x = (layer == 0) ? emb : (layer == 1 ? g_x1 : g_x2);
    int tid = threadIdx.x;
    int rb = blockIdx.x * 64;

    float4* Ws4 = (float4*)Ws;
    const float4* Wg4 = (const float4*)W;
#pragma unroll
    for (int j = tid; j < 1024; j += 256) Ws4[j] = Wg4[j];
    if (tid < 64) { ash[tid] = a_s[tid]; adh[tid] = a_d[tid]; }

    float4* Xs4 = (float4*)Xs;
    const float4* Xg4 = (const float4*)x;
    int nrows = NN - rb; if (nrows > 64) nrows = 64;
#pragma unroll
    for (int j = tid; j < 1024; j += 256) {
        int r = j >> 4;
        Xs4[j] = (r < nrows) ? Xg4[rb * 16 + j] : make_float4(0.f, 0.f, 0.f, 0.f);
    }
    __syncthreads();

    int tx = tid & 15, ty = tid >> 4;
    float4 acc[4];
#pragma unroll
    for (int i = 0; i < 4; i++) acc[i] = make_float4(0.f, 0.f, 0.f, 0.f);

#pragma unroll
    for (int k4 = 0; k4 < 16; k4++) {
        float4 wv0 = Ws4[(4 * k4 + 0) * 16 + tx];
        float4 wv1 = Ws4[(4 * k4 + 1) * 16 + tx];
        float4 wv2 = Ws4[(4 * k4 + 2) * 16 + tx];
        float4 wv3 = Ws4[(4 * k4 + 3) * 16 + tx];
#pragma unroll
        for (int i = 0; i < 4; i++) {
            float4 xv = Xs4[(ty * 4 + i) * 16 + k4];
            acc[i].x = fmaf(xv.x, wv0.x, acc[i].x);
            acc[i].y = fmaf(xv.x, wv0.y, acc[i].y);
            acc[i].z = fmaf(xv.x, wv0.z, acc[i].z);
            acc[i].w = fmaf(xv.x, wv0.w, acc[i].w);
            acc[i].x = fmaf(xv.y, wv1.x, acc[i].x);
            acc[i].y = fmaf(xv.y, wv1.y, acc[i].y);
            acc[i].z = fmaf(xv.y, wv1.z, acc[i].z);
            acc[i].w = fmaf(xv.y, wv1.w, acc[i].w);
            acc[i].x = fmaf(xv.z, wv2.x, acc[i].x);
            acc[i].y = fmaf(xv.z, wv2.y, acc[i].y);
            acc[i].z = fmaf(xv.z, wv2.z, acc[i].z);
            acc[i].w = fmaf(xv.z, wv2.w, acc[i].w);
            acc[i].x = fmaf(xv.w, wv3.x, acc[i].x);
            acc[i].y = fmaf(xv.w, wv3.y, acc[i].y);
            acc[i].z = fmaf(xv.w, wv3.z, acc[i].z);
            acc[i].w = fmaf(xv.w, wv3.w, acc[i].w);
        }
    }

    // store h as fp16 (uint2 = 4 elems), coalesced
    uint2* Hg = (uint2*)g_h16;
#pragma unroll
    for (int i = 0; i < 4; i++) {
        int r = ty * 4 + i;
        if (r < nrows) {
            __half2 lo = __float22half2_rn(make_float2(acc[i].x, acc[i].y));
            __half2 hi = __float22half2_rn(make_float2(acc[i].z, acc[i].w));
            Hg[(rb + r) * 16 + tx] = make_uint2(*(unsigned*)&lo, *(unsigned*)&hi);
        }
    }

    // es/ed partial dots + block max of es
    float4 as4 = ((const float4*)ash)[tx];
    float4 ad4 = ((const float4*)adh)[tx];
    float mmax = -3.4e38f;
#pragma unroll
    for (int i = 0; i < 4; i++) {
        float ps = acc[i].x * as4.x + acc[i].y * as4.y + acc[i].z * as4.z + acc[i].w * as4.w;
        float pd = acc[i].x * ad4.x + acc[i].y * ad4.y + acc[i].z * ad4.z + acc[i].w * ad4.w;
#pragma unroll
        for (int o = 8; o > 0; o >>= 1) {
            ps += __shfl_xor_sync(0xffffffffu, ps, o);
            pd += __shfl_xor_sync(0xffffffffu, pd, o);
        }
        int r = ty * 4 + i;
        if (tx == 0 && r < nrows) { g_es[rb + r] = ps; g_ed[rb + r] = pd; }
        if (r < nrows) mmax = fmaxf(mmax, ps);
    }
#pragma unroll
    for (int o = 16; o > 0; o >>= 1) mmax = fmaxf(mmax, __shfl_xor_sync(0xffffffffu, mmax, o));
    if ((tid & 31) == 0) smax[tid >> 5] = mmax;
    __syncthreads();
    if (tid == 0) {
        float bm = smax[0];
#pragma unroll
        for (int j = 1; j < 8; j++) bm = fmaxf(bm, smax[j]);
        atomicMax(&g_gmaxu[layer], fenc(bm));
    }
}

// ---- aggregate: warp per node, 2 half-warps, fp16 gather, no max pass ----
__global__ void __launch_bounds__(256) k_agg(
    int layer, const float* __restrict__ bias, float* __restrict__ mean_out)
{
    __shared__ float sbias[64];
    __shared__ float s_gmax;
    int tid = threadIdx.x;
    if (tid < 64) sbias[tid] = bias[tid];
    if (tid == 0) s_gmax = fdec(g_gmaxu[layer]);
    __syncthreads();

    int lane = tid & 31;
    int n = blockIdx.x * 8 + (tid >> 5);
    if (n >= NN) return;

    int beg = g_rowptr[n];
    int end = g_rowptr[n + 1];
    float edn = g_ed[n];
    float gm = s_gmax + edn;
    float m = (gm > 0.f) ? gm : 0.2f * gm;   // lrelu monotone => >= segment max

    int half = lane >> 4, hl = lane & 15;
    float denom = 0.f;
    float4 acc = make_float4(0.f, 0.f, 0.f, 0.f);
    const uint2* h2 = (const uint2*)g_h16;

#pragma unroll 4
    for (int k = beg + half; k < end; k += 2) {
        int s = __ldg(&g_csr[k]);
        float e = __ldg(&g_es[s]) + edn;
        e = (e > 0.f) ? e : 0.2f * e;
        float w = __expf(e - m);
        denom += w;
        uint2 hv = h2[s * 16 + hl];          // 4 fp16 elems, 128B/half-warp
        float2 lo = __half22float2(*(__half2*)&hv.x);
        float2 hi = __half22float2(*(__half2*)&hv.y);
        acc.x = fmaf(w, lo.x, acc.x);
        acc.y = fmaf(w, lo.y, acc.y);
        acc.z = fmaf(w, hi.x, acc.z);
        acc.w = fmaf(w, hi.y, acc.w);
    }
    denom += __shfl_xor_sync(0xffffffffu, denom, 16);
    acc.x += __shfl_xor_sync(0xffffffffu, acc.x, 16);
    acc.y += __shfl_xor_sync(0xffffffffu, acc.y, 16);
    acc.z += __shfl_xor_sync(0xffffffffu, acc.z, 16);
    acc.w += __shfl_xor_sync(0xffffffffu, acc.w, 16);

    if (half == 0) {
        float inv = 1.f / (denom + 1e-16f);
        float4 b4 = ((const float4*)sbias)[hl];
        float4 v;
        v.x = acc.x * inv + b4.x;
        v.y = acc.y * inv + b4.y;
        v.z = acc.z * inv + b4.z;
        v.w = acc.w * inv + b4.w;
        v.x = (v.x > 0.f) ? v.x : expm1f(v.x);
        v.y = (v.y > 0.f) ? v.y : expm1f(v.y);
        v.z = (v.z > 0.f) ? v.z : expm1f(v.z);
        v.w = (v.w > 0.f) ? v.w : expm1f(v.w);

        float4* m4 = (float4*)mean_out;
        float4 mo = m4[n * 16 + hl];
        mo.x += v.x; mo.y += v.y; mo.z += v.z; mo.w += v.w;
        if (layer == 2) {
            mo.x *= 0.25f; mo.y *= 0.25f; mo.z *= 0.25f; mo.w *= 0.25f;
        } else {
            float4* xo = (float4*)((layer == 0) ? g_x1 : g_x2);
            xo[n * 16 + hl] = v;
        }
        m4[n * 16 + hl] = mo;
    }
}

extern "C" void kernel_launch(void* const* d_in, const int* in_sizes, int n_in,
                              void* d_out, int out_size) {
    const int*   ei   = (const int*)d_in[0];
    const float* emb  = (const float*)d_in[1];
    const float* W    = (const float*)d_in[2];
    const float* a_s  = (const float*)d_in[3];
    const float* a_d  = (const float*)d_in[4];
    const float* bias = (const float*)d_in[5];
    float* out = (float*)d_out;

    const int* srcs = ei;
    const int* dsts = ei + EE;

    k_init<<<(NN * DD / 4 + 255) / 256, 256>>>((const float4*)emb, (float4*)out);
    k_count<<<(EE / 4 + 255) / 256, 256>>>(dsts);
    k_bsum<<<NB_SCAN, 256>>>();
    k_fillptr<<<NB_SCAN, 256>>>();
    k_fill<<<(ETOT + 255) / 256, 256>>>(srcs, dsts);

    for (int l = 0; l < 3; l++) {
        k_transform<<<(NN + 63) / 64, 256>>>(l, emb, W + l * DD * DD,
                                             a_s + l * DD, a_d + l * DD);
        k_agg<<<(NN + 7) / 8, 256>>>(l, bias + l * DD, out);
    }
}